// round 16
// baseline (speedup 1.0000x reference)
#include <cuda_runtime.h>
#include <cstdint>

// Problem constants
#define B_DIM   8192
#define IN_DIM  256
#define OUT_DIM 256
#define MV      8

// GEMM: C[8192 x 512] = A[8192 x 1024] * Wmat[1024 x 512]
//   A[b][k] = x[b][k/4][comp{0,1,2,4}[k%4]]
//   col n=2i -> y0[:,i], n=2i+1 -> y4[:,i]
#define KDIM    1024
#define NNDIM   512

#define BM      128
#define BN      128
#define KC      32
#define NCHUNK  (KDIM / KC)   // 32
#define NTHR    256           // 8 warps: wm = wrp>>2 (2), wn = wrp&3 (4); warp tile 64x32

// A smem: near-raw x chunk. word addr = m*36 + j*4 + s   (s: comps 0,1,2 | word3 := comp4)
//   fragment LDS banks: 4r + s  -> conflict-free
#define AROW     36
#define AF_WORDS (BM * AROW)            // 4608 words per buffer
#define BF_WORDS 4096                    // 16 KB per buffer
#define SM_WORDS (2 * AF_WORDS + 2 * BF_WORDS)
#define SM_BYTES (SM_WORDS * 4)          // 69632

// Wmat fragment layout: [nblk8][chunk32][kstep4][wn2][nt4][lane32][reg2]
__device__ uint32_t g_Wfrag[NNDIM * KDIM];   // 2 MB, L2-resident

__device__ __forceinline__ uint32_t f2tf32(float f) {
    uint32_t u; asm("cvt.rna.tf32.f32 %0, %1;" : "=r"(u) : "f"(f)); return u;
}
__device__ __forceinline__ uint32_t smem_u32(const void* p) {
    uint32_t a;
    asm("{ .reg .u64 t; cvta.to.shared.u64 t, %1; cvt.u32.u64 %0, t; }" : "=r"(a) : "l"(p));
    return a;
}

// ---- Kernel 1: build W fragments from w (256,256,8) ----
__global__ void wprep_kernel(const float* __restrict__ w)
{
    const int idx = blockIdx.x * blockDim.x + threadIdx.x;   // 524288
    const int reg   = idx & 1;
    const int lane  = (idx >> 1) & 31;
    const int nt    = (idx >> 6) & 3;
    const int wn    = (idx >> 8) & 1;
    const int kstep = (idx >> 9) & 3;
    const int chunk = (idx >> 11) & 31;
    const int nblk  = idx >> 16;
    const int n = nblk * 64 + wn * 32 + nt * 8 + (lane >> 2);
    const int k = chunk * 32 + kstep * 8 + reg * 4 + (lane & 3);
    const int j = k >> 2, s = k & 3, i = n >> 1;
    const float* wr = w + ((size_t)j * OUT_DIM + i) * MV;
    float v = 0.0f;
    if ((n & 1) == 0) {
        if (s < 3) v = wr[s];                 // y0: w0,w1,w2,0
    } else {
        if (s == 1) v = wr[2];                // y4:  x1*w2
        else if (s == 2) v = -wr[1];          //     -x2*w1
        else if (s == 3) v = wr[0];           //      x4*w0
    }
    g_Wfrag[idx] = f2tf32(v);
}

// ---- Kernel 2: tf32 mma.sync GEMM; A & B staged by cp.async ----
__global__ void __launch_bounds__(NTHR, 2)
ga_gemm_kernel(const float* __restrict__ x,
               const float* __restrict__ bias,
               float* __restrict__ out)
{
    extern __shared__ uint32_t sm[];
    // layout: AF buf0 | AF buf1 | BF buf0 | BF buf1

    const int tid  = threadIdx.x;
    const int lane = tid & 31;
    const int wrp  = tid >> 5;
    const int wm   = wrp >> 2;       // 0..1  (M half: 64 rows)
    const int wn   = wrp & 3;        // 0..3  (N quarter: 32 cols)
    const int nhalf = wn >> 1;
    const int wnbit = wn & 1;
    const int bBase = blockIdx.x * BM;
    const int nblk  = blockIdx.y;    // covers n in [nblk*128, nblk*128+128)

    const uint32_t sb_a  = smem_u32(sm);
    const uint32_t sb_bf = smem_u32(sm + 2 * AF_WORDS);

    // accumulators
    float C[4][4][4];
    #pragma unroll
    for (int mt = 0; mt < 4; mt++)
        #pragma unroll
        for (int nt = 0; nt < 4; nt++)
            #pragma unroll
            for (int r = 0; r < 4; r++) C[mt][nt][r] = 0.0f;

    // staging map: thread handles (m = am + 32t, j = aj), t = 0..3
    const int aj = tid & 7;
    const int am = tid >> 3;
    float c4v[4];                    // comp4 values in flight

    auto CPA = [&](int c, int buf) {
        const uint32_t dsta = sb_a + buf * (AF_WORDS * 4);
        #pragma unroll
        for (int t = 0; t < 4; t++) {
            const int m = am + 32 * t;
            const float* src = x + ((size_t)(bBase + m) * IN_DIM + (c * 8 + aj)) * MV;
            asm volatile("cp.async.cg.shared.global [%0], [%1], 16;"
                         :: "r"(dsta + (m * AROW + aj * 4) * 4), "l"(src));
        }
        const uint32_t dstb = sb_bf + buf * (BF_WORDS * 4);
        #pragma unroll
        for (int t = 0; t < 4; t++) {
            const int u = tid + NTHR * t;
            const uint32_t* src = g_Wfrag
                + ((size_t)(2 * nblk + (u >> 9)) * NCHUNK + c) * 2048 + (u & 511) * 4;
            asm volatile("cp.async.cg.shared.global [%0], [%1], 16;"
                         :: "r"(dstb + u * 16), "l"(src));
        }
        asm volatile("cp.async.commit_group;");
    };

    auto LDG4 = [&](int c) {
        #pragma unroll
        for (int t = 0; t < 4; t++) {
            const int m = am + 32 * t;
            c4v[t] = __ldg(x + ((size_t)(bBase + m) * IN_DIM + (c * 8 + aj)) * MV + 4);
        }
    };

    auto STS4 = [&](int buf) {     // overwrite word3 with comp4 (after wait_group!)
        uint32_t* SA = sm + buf * AF_WORDS;
        #pragma unroll
        for (int t = 0; t < 4; t++) {
            const int m = am + 32 * t;
            SA[m * AROW + aj * 4 + 3] = f2tf32(c4v[t]);
        }
    };

    CPA(0, 0);
    LDG4(0);
    asm volatile("cp.async.wait_group 0;");
    STS4(0);
    __syncthreads();

    const int rr = lane >> 2;
    const int ss = lane & 3;

    for (int c = 0; c < NCHUNK; c++) {
        const int buf = c & 1;
        if (c + 1 < NCHUNK) { CPA(c + 1, buf ^ 1); LDG4(c + 1); }

        const uint32_t* SA = sm + buf * AF_WORDS + (wm * 64 + rr) * AROW + ss;
        const uint32_t* SB = sm + 2 * AF_WORDS + buf * BF_WORDS + nhalf * 2048;

        #pragma unroll
        for (int kstep = 0; kstep < 4; kstep++) {
            uint2 b[4];
            #pragma unroll
            for (int nt = 0; nt < 4; nt++)
                b[nt] = *(const uint2*)&SB[(((kstep * 2 + wnbit) * 4 + nt) * 32 + lane) * 2];
            #pragma unroll
            for (int mt = 0; mt < 4; mt++) {
                const uint32_t* pa = SA + (mt * 16) * AROW + kstep * 8;
                uint4 a;
                a.x = pa[0];               // (row,   k)
                a.y = pa[8 * AROW];        // (row+8, k)
                a.z = pa[4];               // (row,   k+4)
                a.w = pa[8 * AROW + 4];    // (row+8, k+4)
                #pragma unroll
                for (int nt = 0; nt < 4; nt++)
                    asm("mma.sync.aligned.m16n8k8.row.col.f32.tf32.tf32.f32 "
                        "{%0,%1,%2,%3}, {%4,%5,%6,%7}, {%8,%9}, {%0,%1,%2,%3};"
                        : "+f"(C[mt][nt][0]), "+f"(C[mt][nt][1]),
                          "+f"(C[mt][nt][2]), "+f"(C[mt][nt][3])
                        : "r"(a.x), "r"(a.y), "r"(a.z), "r"(a.w),
                          "r"(b[nt].x), "r"(b[nt].y));
            }
        }

        if (c + 1 < NCHUNK) {
            asm volatile("cp.async.wait_group 0;");
            STS4(buf ^ 1);
        }
        __syncthreads();
    }

    // ---- epilogue: C frags -> out; c0,c1 = (y0,y4) of i; rows +0/+8
    const int iBase = nblk * 64;
    #pragma unroll
    for (int nt = 0; nt < 4; nt++) {
        const int ig = iBase + wn * 16 + nt * 4 + (lane & 3);
        float4 blo = *(const float4*)(bias + (size_t)ig * MV);
        float4 bhi = *(const float4*)(bias + (size_t)ig * MV + 4);
        #pragma unroll
        for (int mt = 0; mt < 4; mt++) {
            #pragma unroll
            for (int h = 0; h < 2; h++) {
                const int brow = bBase + wm * 64 + mt * 16 + (lane >> 2) + 8 * h;
                float4 v0 = blo; v0.x += C[mt][nt][2 * h];
                float4 v1 = bhi; v1.x += C[mt][nt][2 * h + 1];
                float4* o = (float4*)(out + ((size_t)brow * OUT_DIM + ig) * MV);
                o[0] = v0;
                o[1] = v1;
            }
        }
    }
}

extern "C" void kernel_launch(void* const* d_in, const int* in_sizes, int n_in,
                              void* d_out, int out_size)
{
    const float* x    = (const float*)d_in[0];   // (8192, 256, 8)
    const float* w    = (const float*)d_in[1];   // (256, 256, 8)
    const float* bias = (const float*)d_in[2];   // (256, 8)
    float* out        = (float*)d_out;           // (8192, 256, 8)

    static int attr_set = 0;
    if (!attr_set) {
        cudaFuncSetAttribute(ga_gemm_kernel, cudaFuncAttributeMaxDynamicSharedMemorySize,
                             SM_BYTES);
        attr_set = 1;
    }

    wprep_kernel<<<(NNDIM * KDIM) / 256, 256>>>(w);
    dim3 grid(B_DIM / BM, NNDIM / BN);           // (64, 4) = 256 CTAs
    ga_gemm_kernel<<<grid, NTHR, SM_BYTES>>>(x, bias, out);
}

// round 17
// speedup vs baseline: 1.1873x; 1.1873x over previous
#include <cuda_runtime.h>
#include <cstdint>

// Problem constants
#define B_DIM   8192
#define IN_DIM  256
#define OUT_DIM 256
#define MV      8

// GEMM: C[8192 x 512] = A[8192 x 1024] * Wmat[1024 x 512]
//   A[b][k] = x[b][k/4][comp{0,1,2,4}[k%4]]
//   col n=2i -> y0[:,i], n=2i+1 -> y4[:,i]
#define KDIM    1024
#define NNDIM   512

#define BM      128
#define BN      128
#define KC      32
#define NCHUNK  (KDIM / KC)   // 32
#define NTHR    256           // 8 warps: wm = wrp>>2 (2), wn = wrp&3 (4); warp tile 64x32

// A smem: 16B cell per (m, j): word addr = m*AROW + j*4  (comps x0,x1,x2,x4 raw bits)
// ldmatrix-compatible: matrix rows are the 16B cells.
#define AROW     36
#define AF_WORDS (BM * AROW)            // 4608 words per buffer
#define BF_WORDS 4096                    // 16 KB per buffer
#define SM_WORDS (2 * AF_WORDS + 2 * BF_WORDS)
#define SM_BYTES (SM_WORDS * 4)          // 69632

// Wmat fragment layout: [nblk8][chunk32][kstep4][wn2][nt4][lane32][reg2]
__device__ uint32_t g_Wfrag[NNDIM * KDIM];   // 2 MB, L2-resident

__device__ __forceinline__ uint32_t f2tf32(float f) {
    uint32_t u; asm("cvt.rna.tf32.f32 %0, %1;" : "=r"(u) : "f"(f)); return u;
}
__device__ __forceinline__ uint32_t smem_u32(const void* p) {
    uint32_t a;
    asm("{ .reg .u64 t; cvta.to.shared.u64 t, %1; cvt.u32.u64 %0, t; }" : "=r"(a) : "l"(p));
    return a;
}

// ---- Kernel 1: build W fragments from w (256,256,8) ----
__global__ void wprep_kernel(const float* __restrict__ w)
{
    const int idx = blockIdx.x * blockDim.x + threadIdx.x;   // 524288
    const int reg   = idx & 1;
    const int lane  = (idx >> 1) & 31;
    const int nt    = (idx >> 6) & 3;
    const int wn    = (idx >> 8) & 1;
    const int kstep = (idx >> 9) & 3;
    const int chunk = (idx >> 11) & 31;
    const int nblk  = idx >> 16;
    const int n = nblk * 64 + wn * 32 + nt * 8 + (lane >> 2);
    const int k = chunk * 32 + kstep * 8 + reg * 4 + (lane & 3);
    const int j = k >> 2, s = k & 3, i = n >> 1;
    const float* wr = w + ((size_t)j * OUT_DIM + i) * MV;
    float v = 0.0f;
    if ((n & 1) == 0) {
        if (s < 3) v = wr[s];                 // y0: w0,w1,w2,0
    } else {
        if (s == 1) v = wr[2];                // y4:  x1*w2
        else if (s == 2) v = -wr[1];          //     -x2*w1
        else if (s == 3) v = wr[0];           //      x4*w0
    }
    g_Wfrag[idx] = f2tf32(v);
}

// ---- Kernel 2: tf32 mma.sync GEMM; A raw-bit staged + ldmatrix, B cp.async ----
__global__ void __launch_bounds__(NTHR, 2)
ga_gemm_kernel(const float* __restrict__ x,
               const float* __restrict__ bias,
               float* __restrict__ out)
{
    extern __shared__ uint32_t sm[];
    // layout: AF buf0 | AF buf1 | BF buf0 | BF buf1

    const int tid  = threadIdx.x;
    const int lane = tid & 31;
    const int wrp  = tid >> 5;
    const int wm   = wrp >> 2;       // 0..1  (M half: 64 rows)
    const int wn   = wrp & 3;        // 0..3  (N quarter: 32 cols)
    const int nhalf = wn >> 1;
    const int wnbit = wn & 1;
    const int bBase = blockIdx.x * BM;
    const int nblk  = blockIdx.y;    // covers n in [nblk*128, nblk*128+128)

    const uint32_t sb_a  = smem_u32(sm);
    const uint32_t sb_bf = smem_u32(sm + 2 * AF_WORDS);

    // accumulators
    float C[4][4][4];
    #pragma unroll
    for (int mt = 0; mt < 4; mt++)
        #pragma unroll
        for (int nt = 0; nt < 4; nt++)
            #pragma unroll
            for (int r = 0; r < 4; r++) C[mt][nt][r] = 0.0f;

    // A staging map: thread handles (m = am + 32t, j = aj)
    const int aj = tid & 7;
    const int am = tid >> 3;         // 0..31
    uint4 vA[4];                     // raw bits {x0,x1,x2,x4}

    auto CPA_B = [&](int c, int buf) {
        const uint32_t dstb = sb_bf + buf * (BF_WORDS * 4);
        #pragma unroll
        for (int t = 0; t < 4; t++) {
            const int u = tid + NTHR * t;
            const uint32_t* src = g_Wfrag
                + ((size_t)(2 * nblk + (u >> 9)) * NCHUNK + c) * 2048 + (u & 511) * 4;
            asm volatile("cp.async.cg.shared.global [%0], [%1], 16;"
                         :: "r"(dstb + u * 16), "l"(src));
        }
        asm volatile("cp.async.commit_group;");
    };

    auto LOADA = [&](int c) {
        #pragma unroll
        for (int t = 0; t < 4; t++) {
            const int m = am + 32 * t;
            const float* src = x + ((size_t)(bBase + m) * IN_DIM + (c * 8 + aj)) * MV;
            float4 lo = *(const float4*)src;
            float  x4 = src[4];
            vA[t].x = __float_as_uint(lo.x);
            vA[t].y = __float_as_uint(lo.y);
            vA[t].z = __float_as_uint(lo.z);
            vA[t].w = __float_as_uint(x4);
        }
    };

    auto STOREA = [&](int buf) {
        uint32_t* SA = sm + buf * AF_WORDS;
        #pragma unroll
        for (int t = 0; t < 4; t++) {
            const int m = am + 32 * t;
            *(uint4*)(SA + m * AROW + aj * 4) = vA[t];   // STS.128, raw bits
        }
    };

    // ldmatrix per-lane row address (words, within buffer):
    //   q = lane>>3 selects matrix: q&1 -> +8 rows, q>>1 -> khalf (j odd)
    const int q    = lane >> 3;
    const int rowl = lane & 7;
    const int aoff = (wm * 64 + (q & 1) * 8 + rowl) * AROW + (q >> 1) * 4;

    CPA_B(0, 0);
    LOADA(0);
    STOREA(0);
    asm volatile("cp.async.wait_group 0;");
    __syncthreads();

    for (int c = 0; c < NCHUNK; c++) {
        const int buf = c & 1;
        if (c + 1 < NCHUNK) { CPA_B(c + 1, buf ^ 1); LOADA(c + 1); }

        const uint32_t abase = sb_a + buf * (AF_WORDS * 4) + aoff * 4;
        const uint32_t* SB = sm + 2 * AF_WORDS + buf * BF_WORDS + nhalf * 2048;

        #pragma unroll
        for (int kstep = 0; kstep < 4; kstep++) {
            uint2 b[4];
            #pragma unroll
            for (int nt = 0; nt < 4; nt++)
                b[nt] = *(const uint2*)&SB[(((kstep * 2 + wnbit) * 4 + nt) * 32 + lane) * 2];
            #pragma unroll
            for (int mt = 0; mt < 4; mt++) {
                uint4 a;
                const uint32_t addr = abase + (mt * 16 * AROW + kstep * 8) * 4;
                asm volatile("ldmatrix.sync.aligned.m8n8.x4.shared.b16 {%0,%1,%2,%3}, [%4];"
                             : "=r"(a.x), "=r"(a.y), "=r"(a.z), "=r"(a.w) : "r"(addr));
                #pragma unroll
                for (int nt = 0; nt < 4; nt++)
                    asm("mma.sync.aligned.m16n8k8.row.col.f32.tf32.tf32.f32 "
                        "{%0,%1,%2,%3}, {%4,%5,%6,%7}, {%8,%9}, {%0,%1,%2,%3};"
                        : "+f"(C[mt][nt][0]), "+f"(C[mt][nt][1]),
                          "+f"(C[mt][nt][2]), "+f"(C[mt][nt][3])
                        : "r"(a.x), "r"(a.y), "r"(a.z), "r"(a.w),
                          "r"(b[nt].x), "r"(b[nt].y));
            }
        }

        if (c + 1 < NCHUNK) STOREA(buf ^ 1);
        asm volatile("cp.async.wait_group 0;");
        __syncthreads();
    }

    // ---- epilogue: C frags -> out; c0,c1 = (y0,y4) of i; rows +0/+8
    const int iBase = nblk * 64;
    #pragma unroll
    for (int nt = 0; nt < 4; nt++) {
        const int ig = iBase + wn * 16 + nt * 4 + (lane & 3);
        float4 blo = *(const float4*)(bias + (size_t)ig * MV);
        float4 bhi = *(const float4*)(bias + (size_t)ig * MV + 4);
        #pragma unroll
        for (int mt = 0; mt < 4; mt++) {
            #pragma unroll
            for (int h = 0; h < 2; h++) {
                const int brow = bBase + wm * 64 + mt * 16 + (lane >> 2) + 8 * h;
                float4 v0 = blo; v0.x += C[mt][nt][2 * h];
                float4 v1 = bhi; v1.x += C[mt][nt][2 * h + 1];
                float4* o = (float4*)(out + ((size_t)brow * OUT_DIM + ig) * MV);
                o[0] = v0;
                o[1] = v1;
            }
        }
    }
}

extern "C" void kernel_launch(void* const* d_in, const int* in_sizes, int n_in,
                              void* d_out, int out_size)
{
    const float* x    = (const float*)d_in[0];   // (8192, 256, 8)
    const float* w    = (const float*)d_in[1];   // (256, 256, 8)
    const float* bias = (const float*)d_in[2];   // (256, 8)
    float* out        = (float*)d_out;           // (8192, 256, 8)

    static int attr_set = 0;
    if (!attr_set) {
        cudaFuncSetAttribute(ga_gemm_kernel, cudaFuncAttributeMaxDynamicSharedMemorySize,
                             SM_BYTES);
        attr_set = 1;
    }

    wprep_kernel<<<(NNDIM * KDIM) / 256, 256>>>(w);
    dim3 grid(B_DIM / BM, NNDIM / BN);           // (64, 4) = 256 CTAs
    ga_gemm_kernel<<<grid, NTHR, SM_BYTES>>>(x, bias, out);
}